// round 1
// baseline (speedup 1.0000x reference)
#include <cuda_runtime.h>
#include <cstdint>
#include <cstdio>

// Problem constants
#define GB 64
#define GN 196
#define GD 768
#define GH 12
#define GHD 64
#define GSIDE 14
#define GM (GB*GN)   // 12544

// Scratch (device globals: allocation-free rule)
__device__ __align__(16) float g_q[GB*GH*GN*GHD];
__device__ __align__(16) float g_k[GB*GH*GN*GHD];
__device__ __align__(16) float g_v[GB*GH*GN*GHD];
__device__ __align__(16) float g_ctx[(size_t)GM*GD];

// ---------------- packed f32x2 helpers (Blackwell FFMA2 path) ----------------
__device__ __forceinline__ unsigned long long pack2(float x, float y) {
    unsigned long long r;
    asm("mov.b64 %0, {%1, %2};" : "=l"(r) : "f"(x), "f"(y));
    return r;
}
__device__ __forceinline__ void fma2(unsigned long long& d, unsigned long long a, unsigned long long b) {
    asm("fma.rn.f32x2 %0, %1, %2, %0;" : "+l"(d) : "l"(a), "l"(b));
}

// ---------------- SGEMM: C[M,N] = A[M,K] @ B[K,N] + bias -------------------
// 128x128 block tile, BK=8, 256 threads, 8x8 per thread, f32x2 accumulators.
// headmode=1: scatter output into [B,H,N,HD] head-major layout.
__global__ void __launch_bounds__(256, 2)
sgemm_f32x2(const float* __restrict__ A, const float* __restrict__ B,
            const float* __restrict__ bias, float* __restrict__ C,
            int headmode)
{
    const int N = GD, K = GD;
    __shared__ float As[8][128];
    __shared__ float Bs[8][128];

    const int tid  = threadIdx.x;
    const int bx   = blockIdx.x, by = blockIdx.y;
    const int arow = tid >> 1;
    const int acol = (tid & 1) << 2;
    const int brow = tid >> 5;
    const int bcol = (tid & 31) << 2;
    const int ty   = tid >> 4, tx = tid & 15;

    const float* Ap = A + (size_t)(by*128 + arow)*K + acol;
    const float* Bp = B + (size_t)brow*N + bx*128 + bcol;

    unsigned long long acc2[8][4];
    #pragma unroll
    for (int i = 0; i < 8; i++)
        #pragma unroll
        for (int c = 0; c < 4; c++) acc2[i][c] = 0ull;

    for (int k0 = 0; k0 < K; k0 += 8) {
        float4 av = *(const float4*)(Ap + k0);
        float4 bv = *(const float4*)(Bp + (size_t)k0*N);
        __syncthreads();
        As[acol+0][arow] = av.x;
        As[acol+1][arow] = av.y;
        As[acol+2][arow] = av.z;
        As[acol+3][arow] = av.w;
        *(float4*)&Bs[brow][bcol] = bv;
        __syncthreads();

        #pragma unroll
        for (int k = 0; k < 8; k++) {
            float4 a0 = *(const float4*)&As[k][ty*8];
            float4 a1 = *(const float4*)&As[k][ty*8+4];
            float4 b0 = *(const float4*)&Bs[k][tx*8];
            float4 b1 = *(const float4*)&Bs[k][tx*8+4];
            unsigned long long b2[4];
            b2[0] = pack2(b0.x, b0.y); b2[1] = pack2(b0.z, b0.w);
            b2[2] = pack2(b1.x, b1.y); b2[3] = pack2(b1.z, b1.w);
            float af[8] = {a0.x, a0.y, a0.z, a0.w, a1.x, a1.y, a1.z, a1.w};
            #pragma unroll
            for (int i = 0; i < 8; i++) {
                unsigned long long a2 = pack2(af[i], af[i]);
                fma2(acc2[i][0], a2, b2[0]);
                fma2(acc2[i][1], a2, b2[1]);
                fma2(acc2[i][2], a2, b2[2]);
                fma2(acc2[i][3], a2, b2[3]);
            }
        }
    }

    #pragma unroll
    for (int i = 0; i < 8; i++) {
        int row = by*128 + ty*8 + i;
        int bb = row / GN, nn = row % GN;
        #pragma unroll
        for (int c = 0; c < 4; c++) {
            int col = bx*128 + tx*8 + 2*c;
            float lo = __uint_as_float((unsigned)(acc2[i][c] & 0xffffffffull));
            float hi = __uint_as_float((unsigned)(acc2[i][c] >> 32));
            lo += bias[col];
            hi += bias[col + 1];
            if (headmode) {
                int h0 = col >> 6, hd0 = col & 63;  // pair never crosses head boundary
                size_t base = (((size_t)bb*GH + h0)*GN + nn)*GHD + hd0;
                C[base]     = lo;
                C[base + 1] = hi;
            } else {
                size_t base = (size_t)row*N + col;
                C[base]     = lo;
                C[base + 1] = hi;
            }
        }
    }
}

// ---------------- Attention core: one CTA per (b,h) ------------------------
// SMEM: Kt [64][200] (transposed, padded), V [196][64], Q [196][64],
//       P [16 warps][4 rows][196].
#define KT_STRIDE 200
#define ATT_SMEM_FLOATS (GHD*KT_STRIDE + GN*GHD + GN*GHD + 16*4*GN)
#define ATT_SMEM_BYTES  (ATT_SMEM_FLOATS*4)

__global__ void __launch_bounds__(512, 1)
attn_kernel(const float* __restrict__ Q, const float* __restrict__ K,
            const float* __restrict__ V, const float* __restrict__ Wsig,
            const float* __restrict__ bsigp, const float* __restrict__ tempp,
            float* __restrict__ CTX)
{
    extern __shared__ float sm[];
    float* Ks = sm;                       // [64][200]
    float* Vs = Ks + GHD*KT_STRIDE;       // [196][64]
    float* Qs = Vs + GN*GHD;              // [196][64]
    float* Ps = Qs + GN*GHD;              // [16][4][196]

    const int bh = blockIdx.x;
    const int b = bh / GH, h = bh % GH;
    const float* Qg = Q + (size_t)bh * GN * GHD;
    const float* Kg = K + (size_t)bh * GN * GHD;
    const float* Vg = V + (size_t)bh * GN * GHD;

    const int tid = threadIdx.x;

    for (int idx = tid; idx < GN*GHD; idx += 512) {
        int j = idx >> 6, d = idx & 63;
        Ks[d*KT_STRIDE + j] = Kg[idx];
        Vs[idx] = Vg[idx];
        Qs[idx] = Qg[idx];
    }
    __syncthreads();

    const int wid = tid >> 5, lane = tid & 31;
    const float temperature = tempp[0];
    const float bs = bsigp[0];
    const float ws_lo = Wsig[lane];
    const float ws_hi = Wsig[32 + lane];

    for (int p = wid; p < GN/4; p += 16) {
        const int i0 = p * 4;

        // ---- per-row sigma -> denom ----
        float denom[4];
        #pragma unroll
        for (int r = 0; r < 4; r++) {
            int i = i0 + r;
            float part = Qs[i*64 + lane] * ws_lo + Qs[i*64 + 32 + lane] * ws_hi;
            #pragma unroll
            for (int o = 16; o > 0; o >>= 1)
                part += __shfl_xor_sync(0xffffffffu, part, o);
            float x = part + bs;
            float sp = (x > 20.f) ? x : log1pf(expf(x));
            float sig = sp + 1e-3f;
            float st = sig * temperature;
            denom[r] = 2.f * st * st;
        }

        // ---- raw scores: 4 rows x 7 keys per lane ----
        float acc[4][7];
        #pragma unroll
        for (int r = 0; r < 4; r++)
            #pragma unroll
            for (int t = 0; t < 7; t++) acc[r][t] = 0.f;

        #pragma unroll 4
        for (int d4 = 0; d4 < 64; d4 += 4) {
            float4 qv[4];
            #pragma unroll
            for (int r = 0; r < 4; r++)
                qv[r] = *(const float4*)&Qs[(i0 + r)*64 + d4];
            const float* kr = Ks + d4*KT_STRIDE;
            #pragma unroll
            for (int dd = 0; dd < 4; dd++) {
                float q0 = dd==0 ? qv[0].x : dd==1 ? qv[0].y : dd==2 ? qv[0].z : qv[0].w;
                float q1 = dd==0 ? qv[1].x : dd==1 ? qv[1].y : dd==2 ? qv[1].z : qv[1].w;
                float q2 = dd==0 ? qv[2].x : dd==1 ? qv[2].y : dd==2 ? qv[2].z : qv[2].w;
                float q3 = dd==0 ? qv[3].x : dd==1 ? qv[3].y : dd==2 ? qv[3].z : qv[3].w;
                #pragma unroll
                for (int t = 0; t < 7; t++) {
                    // j up to 223 reads past Ks row into Vs region: finite garbage,
                    // masked out below before any use.
                    float kv = kr[dd*KT_STRIDE + lane + 32*t];
                    acc[0][t] += q0*kv;
                    acc[1][t] += q1*kv;
                    acc[2][t] += q2*kv;
                    acc[3][t] += q3*kv;
                }
            }
        }

        // ---- gaussian mask * score, softmax, write probs ----
        #pragma unroll
        for (int r = 0; r < 4; r++) {
            const int i = i0 + r;
            const int iy = i / GSIDE, ix = i % GSIDE;
            const float inv_denom = -1.f / denom[r];
            float mx = -1e30f;
            #pragma unroll
            for (int t = 0; t < 7; t++) {
                int j = lane + 32*t;
                if (j < GN) {
                    int jy = j / GSIDE, jx = j % GSIDE;
                    float dy = (float)(iy - jy), dx = (float)(ix - jx);
                    float d2 = dy*dy + dx*dx;
                    float val = __expf(d2 * inv_denom) * (acc[r][t] * 0.125f);
                    acc[r][t] = val;
                    mx = fmaxf(mx, val);
                } else {
                    acc[r][t] = -1e30f;
                }
            }
            #pragma unroll
            for (int o = 16; o > 0; o >>= 1)
                mx = fmaxf(mx, __shfl_xor_sync(0xffffffffu, mx, o));
            float sum = 0.f;
            #pragma unroll
            for (int t = 0; t < 7; t++) {
                int j = lane + 32*t;
                if (j < GN) {
                    float e = __expf(acc[r][t] - mx);
                    acc[r][t] = e;
                    sum += e;
                }
            }
            #pragma unroll
            for (int o = 16; o > 0; o >>= 1)
                sum += __shfl_xor_sync(0xffffffffu, sum, o);
            float inv = 1.f / sum;
            float* prow = Ps + (size_t)(wid*4 + r)*GN;
            #pragma unroll
            for (int t = 0; t < 7; t++) {
                int j = lane + 32*t;
                if (j < GN) prow[j] = acc[r][t] * inv;
            }
        }
        __syncwarp();

        // ---- ctx = P @ V : lane owns dims (lane, lane+32) ----
        float cA0=0.f,cB0=0.f,cA1=0.f,cB1=0.f,cA2=0.f,cB2=0.f,cA3=0.f,cB3=0.f;
        const float* p0 = Ps + (size_t)(wid*4 + 0)*GN;
        const float* p1 = Ps + (size_t)(wid*4 + 1)*GN;
        const float* p2 = Ps + (size_t)(wid*4 + 2)*GN;
        const float* p3 = Ps + (size_t)(wid*4 + 3)*GN;
        for (int j = 0; j < GN; j += 4) {
            float4 pp0 = *(const float4*)(p0 + j);
            float4 pp1 = *(const float4*)(p1 + j);
            float4 pp2 = *(const float4*)(p2 + j);
            float4 pp3 = *(const float4*)(p3 + j);
            #pragma unroll
            for (int jj = 0; jj < 4; jj++) {
                float v0 = Vs[(j + jj)*64 + lane];
                float v1 = Vs[(j + jj)*64 + lane + 32];
                float w0 = jj==0 ? pp0.x : jj==1 ? pp0.y : jj==2 ? pp0.z : pp0.w;
                float w1 = jj==0 ? pp1.x : jj==1 ? pp1.y : jj==2 ? pp1.z : pp1.w;
                float w2 = jj==0 ? pp2.x : jj==1 ? pp2.y : jj==2 ? pp2.z : pp2.w;
                float w3 = jj==0 ? pp3.x : jj==1 ? pp3.y : jj==2 ? pp3.z : pp3.w;
                cA0 += w0*v0; cB0 += w0*v1;
                cA1 += w1*v0; cB1 += w1*v1;
                cA2 += w2*v0; cB2 += w2*v1;
                cA3 += w3*v0; cB3 += w3*v1;
            }
        }

        // ---- store ctx in [B,N,D] merged-head layout ----
        {
            size_t base = ((size_t)(b*GN + i0))*GD + h*GHD;
            CTX[base + lane]                = cA0;
            CTX[base + lane + 32]           = cB0;
            CTX[base + GD + lane]           = cA1;
            CTX[base + GD + lane + 32]      = cB1;
            CTX[base + 2*GD + lane]         = cA2;
            CTX[base + 2*GD + lane + 32]    = cB2;
            CTX[base + 3*GD + lane]         = cA3;
            CTX[base + 3*GD + lane + 32]    = cB3;
        }
    }
}

// ---------------- launch ----------------------------------------------------
extern "C" void kernel_launch(void* const* d_in, const int* in_sizes, int n_in,
                              void* d_out, int out_size)
{
    const float* hs   = (const float*)d_in[0];
    const float* temp = (const float*)d_in[1];
    const float* Wq   = (const float*)d_in[2];
    const float* bq   = (const float*)d_in[3];
    const float* Wk   = (const float*)d_in[4];
    const float* bk   = (const float*)d_in[5];
    const float* Wv   = (const float*)d_in[6];
    const float* bv   = (const float*)d_in[7];
    const float* Wo   = (const float*)d_in[8];
    const float* bo   = (const float*)d_in[9];
    const float* Wsig = (const float*)d_in[10];
    const float* bsig = (const float*)d_in[11];
    float* out = (float*)d_out;

    float *gq, *gk, *gv, *gctx;
    cudaGetSymbolAddress((void**)&gq,   g_q);
    cudaGetSymbolAddress((void**)&gk,   g_k);
    cudaGetSymbolAddress((void**)&gv,   g_v);
    cudaGetSymbolAddress((void**)&gctx, g_ctx);

    cudaFuncSetAttribute(attn_kernel,
                         cudaFuncAttributeMaxDynamicSharedMemorySize,
                         ATT_SMEM_BYTES);

    dim3 gg(GD/128, GM/128);   // (6, 98)
    sgemm_f32x2<<<gg, 256>>>(hs,   Wq, bq, gq,  1);
    sgemm_f32x2<<<gg, 256>>>(hs,   Wk, bk, gk,  1);
    sgemm_f32x2<<<gg, 256>>>(hs,   Wv, bv, gv,  1);
    attn_kernel<<<GB*GH, 512, ATT_SMEM_BYTES>>>(gq, gk, gv, Wsig, bsig, temp, gctx);
    sgemm_f32x2<<<gg, 256>>>(gctx, Wo, bo, out, 0);
}

// round 3
// speedup vs baseline: 2.3530x; 2.3530x over previous
#include <cuda_runtime.h>
#include <cstdint>
#include <cstdio>

// Problem constants
#define GB 64
#define GN 196
#define GD 768
#define GH 12
#define GHD 64
#define GSIDE 14
#define GM (GB*GN)   // 12544

// Scratch (device globals: allocation-free rule)
__device__ __align__(16) float g_q[GB*GH*GN*GHD];
__device__ __align__(16) float g_k[GB*GH*GN*GHD];
__device__ __align__(16) float g_v[GB*GH*GN*GHD];
__device__ __align__(16) float g_ctx[(size_t)GM*GD];
__device__ __align__(16) float g_hs[(size_t)GM*GD];   // tf32-rounded hidden states
__device__ __align__(16) float g_w[4*GD*GD];          // tf32-rounded weights (untransposed)

// ============================ helpers =======================================
__device__ __forceinline__ uint32_t smem_u32(const void* p) {
    uint32_t a;
    asm("{ .reg .u64 t; cvta.to.shared.u64 t, %1; cvt.u32.u64 %0, t; }" : "=r"(a) : "l"(p));
    return a;
}
__device__ __forceinline__ void cp16(uint32_t s, const void* g) {
    asm volatile("cp.async.cg.shared.global [%0], [%1], 16;" :: "r"(s), "l"(g));
}
__device__ __forceinline__ void cp_commit() { asm volatile("cp.async.commit_group;" ::: "memory"); }
__device__ __forceinline__ void cp_wait1()  { asm volatile("cp.async.wait_group 1;"  ::: "memory"); }

__device__ __forceinline__ uint32_t tf32_rna(float f) {
    uint32_t u;
    asm("cvt.rna.tf32.f32 %0, %1;" : "=r"(u) : "f"(f));
    return u;
}

__device__ __forceinline__ void mma_tf32(float* c, const uint32_t* a, const uint32_t* b) {
    asm volatile(
        "mma.sync.aligned.m16n8k8.row.col.f32.tf32.tf32.f32 "
        "{%0,%1,%2,%3}, {%4,%5,%6,%7}, {%8,%9}, {%0,%1,%2,%3};"
        : "+f"(c[0]), "+f"(c[1]), "+f"(c[2]), "+f"(c[3])
        : "r"(a[0]), "r"(a[1]), "r"(a[2]), "r"(a[3]), "r"(b[0]), "r"(b[1]));
}

// ===================== tf32 rounding pre-pass ===============================
__global__ void round_tf32(const float* __restrict__ s, float* __restrict__ d, int n4) {
    int i = blockIdx.x * blockDim.x + threadIdx.x;
    if (i < n4) {
        float4 v = ((const float4*)s)[i];
        v.x = __uint_as_float(tf32_rna(v.x));
        v.y = __uint_as_float(tf32_rna(v.y));
        v.z = __uint_as_float(tf32_rna(v.z));
        v.w = __uint_as_float(tf32_rna(v.w));
        ((float4*)d)[i] = v;
    }
}

// ===================== tf32 mma.sync GEMM ===================================
// C[M,768] = A[M,768] @ B[768,768] (+bias). B row-major [K][N] (natural weight
// layout == col-major k8n8 operand layout). 128x128x32 tiles, 256 thr, 8 warps
// as 4(m) x 2(n), warp tile 32x64, m16n8k8 fragments via scalar LDS
// (conflict-free: A stride 36, B stride 136).
#define BM 128
#define BN 128
#define BK 32
#define AST 36
#define BST 136
#define ASZ (BM*AST)
#define BSZ (BK*BST)
#define GEMM_SMEM ((2*ASZ + 2*BSZ)*4)    // 71680 B
#define NCH (GD/BK)                       // 24

__global__ void __launch_bounds__(256, 2)
mma_gemm(const float* __restrict__ A, const float* __restrict__ B,
         const float* __restrict__ bias, float* __restrict__ C, int headmode)
{
    extern __shared__ float smf[];
    float* As = smf;               // [2][BM][AST]
    float* Bs = smf + 2*ASZ;       // [2][BK][BST]
    const uint32_t abase = smem_u32(As);
    const uint32_t bbase = smem_u32(Bs);

    const int tid = threadIdx.x;
    const int bx = blockIdx.x, by = blockIdx.y;
    const float* Ag = A + (size_t)(by*BM)*GD;
    const float* Bg = B + bx*BN;

    auto loadA = [&](int c, int buf) {
        const float* ag = Ag + c*BK;
        const uint32_t dst = abase + buf*ASZ*4;
        #pragma unroll
        for (int it = 0; it < 4; it++) {
            int idx = tid + 256*it;           // 0..1023
            int m = idx >> 3, k4 = idx & 7;
            cp16(dst + (m*AST + k4*4)*4, ag + (size_t)m*GD + k4*4);
        }
    };
    auto loadB = [&](int c, int buf) {
        const float* bg = Bg + (size_t)(c*BK)*GD;
        const uint32_t dst = bbase + buf*BSZ*4;
        #pragma unroll
        for (int it = 0; it < 4; it++) {
            int idx = tid + 256*it;           // 0..1023
            int k = idx >> 5, n4 = idx & 31;
            cp16(dst + (k*BST + n4*4)*4, bg + (size_t)k*GD + n4*4);
        }
    };

    loadA(0, 0); loadB(0, 0); cp_commit();
    loadA(1, 1); loadB(1, 1); cp_commit();

    const int wid = tid >> 5, lane = tid & 31;
    const int wm = wid & 3, wn = wid >> 2;     // 4 x 2 warp grid
    const int lr = lane >> 2, lq = lane & 3;

    float acc[2][8][4];
    #pragma unroll
    for (int i = 0; i < 2; i++)
        #pragma unroll
        for (int j = 0; j < 8; j++)
            #pragma unroll
            for (int k = 0; k < 4; k++) acc[i][j][k] = 0.f;

    for (int c = 0; c < NCH; c++) {
        cp_wait1();
        __syncthreads();
        const int buf = c & 1;
        const float* as = As + buf*ASZ;
        const float* bs = Bs + buf*BSZ;

        #pragma unroll
        for (int s = 0; s < 4; s++) {
            const int k0 = s*8 + lq;
            uint32_t a[2][4], b[8][2];
            #pragma unroll
            for (int mt = 0; mt < 2; mt++) {
                const int r = wm*32 + mt*16 + lr;
                a[mt][0] = __float_as_uint(as[r*AST + k0]);
                a[mt][1] = __float_as_uint(as[(r+8)*AST + k0]);
                a[mt][2] = __float_as_uint(as[r*AST + k0 + 4]);
                a[mt][3] = __float_as_uint(as[(r+8)*AST + k0 + 4]);
            }
            #pragma unroll
            for (int nt = 0; nt < 8; nt++) {
                const int n = wn*64 + nt*8 + lr;
                b[nt][0] = __float_as_uint(bs[k0*BST + n]);
                b[nt][1] = __float_as_uint(bs[(k0+4)*BST + n]);
            }
            #pragma unroll
            for (int mt = 0; mt < 2; mt++)
                #pragma unroll
                for (int nt = 0; nt < 8; nt++)
                    mma_tf32(acc[mt][nt], a[mt], b[nt]);
        }
        __syncthreads();
        if (c + 2 < NCH) { loadA(c+2, buf); loadB(c+2, buf); }
        cp_commit();   // empty group at tail keeps wait_group bookkeeping aligned
    }

    // Epilogue: c0,c1 at (row=lr, col=2*lq,+1); c2,c3 at row lr+8.
    #pragma unroll
    for (int mt = 0; mt < 2; mt++) {
        #pragma unroll
        for (int h8 = 0; h8 < 2; h8++) {
            const int row = by*BM + wm*32 + mt*16 + h8*8 + lr;
            const int bb = row / GN, nn = row % GN;
            #pragma unroll
            for (int nt = 0; nt < 8; nt++) {
                const int col = bx*BN + wn*64 + nt*8 + 2*lq;
                float2 v;
                v.x = acc[mt][nt][h8*2+0] + bias[col];
                v.y = acc[mt][nt][h8*2+1] + bias[col+1];
                if (headmode) {
                    const int h = col >> 6, hd = col & 63;
                    *(float2*)(C + (((size_t)bb*GH + h)*GN + nn)*GHD + hd) = v;
                } else {
                    *(float2*)(C + (size_t)row*GD + col) = v;
                }
            }
        }
    }
}

// ---------------- Attention core: one CTA per (b,h) ------------------------
#define KT_STRIDE 200
#define ATT_SMEM_FLOATS (GHD*KT_STRIDE + GN*GHD + GN*GHD + 16*4*GN)
#define ATT_SMEM_BYTES  (ATT_SMEM_FLOATS*4)

__global__ void __launch_bounds__(512, 1)
attn_kernel(const float* __restrict__ Q, const float* __restrict__ K,
            const float* __restrict__ V, const float* __restrict__ Wsig,
            const float* __restrict__ bsigp, const float* __restrict__ tempp,
            float* __restrict__ CTX)
{
    extern __shared__ float smf[];
    float* Ks = smf;                      // [64][200]
    float* Vs = Ks + GHD*KT_STRIDE;       // [196][64]
    float* Qs = Vs + GN*GHD;              // [196][64]
    float* Ps = Qs + GN*GHD;              // [16][4][196]

    const int bh = blockIdx.x;
    const int b = bh / GH, h = bh % GH;
    const float* Qg = Q + (size_t)bh * GN * GHD;
    const float* Kg = K + (size_t)bh * GN * GHD;
    const float* Vg = V + (size_t)bh * GN * GHD;

    const int tid = threadIdx.x;

    for (int idx = tid; idx < GN*GHD; idx += 512) {
        int j = idx >> 6, d = idx & 63;
        Ks[d*KT_STRIDE + j] = Kg[idx];
        Vs[idx] = Vg[idx];
        Qs[idx] = Qg[idx];
    }
    __syncthreads();

    const int wid = tid >> 5, lane = tid & 31;
    const float temperature = tempp[0];
    const float bs = bsigp[0];
    const float ws_lo = Wsig[lane];
    const float ws_hi = Wsig[32 + lane];

    for (int p = wid; p < GN/4; p += 16) {
        const int i0 = p * 4;

        float denom[4];
        #pragma unroll
        for (int r = 0; r < 4; r++) {
            int i = i0 + r;
            float part = Qs[i*64 + lane] * ws_lo + Qs[i*64 + 32 + lane] * ws_hi;
            #pragma unroll
            for (int o = 16; o > 0; o >>= 1)
                part += __shfl_xor_sync(0xffffffffu, part, o);
            float x = part + bs;
            float sp = (x > 20.f) ? x : log1pf(expf(x));
            float sig = sp + 1e-3f;
            float st = sig * temperature;
            denom[r] = 2.f * st * st;
        }

        float acc[4][7];
        #pragma unroll
        for (int r = 0; r < 4; r++)
            #pragma unroll
            for (int t = 0; t < 7; t++) acc[r][t] = 0.f;

        #pragma unroll 4
        for (int d4 = 0; d4 < 64; d4 += 4) {
            float4 qv[4];
            #pragma unroll
            for (int r = 0; r < 4; r++)
                qv[r] = *(const float4*)&Qs[(i0 + r)*64 + d4];
            const float* kr = Ks + d4*KT_STRIDE;
            #pragma unroll
            for (int dd = 0; dd < 4; dd++) {
                float q0 = dd==0 ? qv[0].x : dd==1 ? qv[0].y : dd==2 ? qv[0].z : qv[0].w;
                float q1 = dd==0 ? qv[1].x : dd==1 ? qv[1].y : dd==2 ? qv[1].z : qv[1].w;
                float q2 = dd==0 ? qv[2].x : dd==1 ? qv[2].y : dd==2 ? qv[2].z : qv[2].w;
                float q3 = dd==0 ? qv[3].x : dd==1 ? qv[3].y : dd==2 ? qv[3].z : qv[3].w;
                #pragma unroll
                for (int t = 0; t < 7; t++) {
                    float kv = kr[dd*KT_STRIDE + lane + 32*t];
                    acc[0][t] += q0*kv;
                    acc[1][t] += q1*kv;
                    acc[2][t] += q2*kv;
                    acc[3][t] += q3*kv;
                }
            }
        }

        #pragma unroll
        for (int r = 0; r < 4; r++) {
            const int i = i0 + r;
            const int iy = i / GSIDE, ix = i % GSIDE;
            const float inv_denom = -1.f / denom[r];
            float mx = -1e30f;
            #pragma unroll
            for (int t = 0; t < 7; t++) {
                int j = lane + 32*t;
                if (j < GN) {
                    int jy = j / GSIDE, jx = j % GSIDE;
                    float dy = (float)(iy - jy), dx = (float)(ix - jx);
                    float d2 = dy*dy + dx*dx;
                    float val = __expf(d2 * inv_denom) * (acc[r][t] * 0.125f);
                    acc[r][t] = val;
                    mx = fmaxf(mx, val);
                } else {
                    acc[r][t] = -1e30f;
                }
            }
            #pragma unroll
            for (int o = 16; o > 0; o >>= 1)
                mx = fmaxf(mx, __shfl_xor_sync(0xffffffffu, mx, o));
            float sum = 0.f;
            #pragma unroll
            for (int t = 0; t < 7; t++) {
                int j = lane + 32*t;
                if (j < GN) {
                    float e = __expf(acc[r][t] - mx);
                    acc[r][t] = e;
                    sum += e;
                }
            }
            #pragma unroll
            for (int o = 16; o > 0; o >>= 1)
                sum += __shfl_xor_sync(0xffffffffu, sum, o);
            float inv = 1.f / sum;
            float* prow = Ps + (size_t)(wid*4 + r)*GN;
            #pragma unroll
            for (int t = 0; t < 7; t++) {
                int j = lane + 32*t;
                if (j < GN) prow[j] = acc[r][t] * inv;
            }
        }
        __syncwarp();

        float cA0=0.f,cB0=0.f,cA1=0.f,cB1=0.f,cA2=0.f,cB2=0.f,cA3=0.f,cB3=0.f;
        const float* p0 = Ps + (size_t)(wid*4 + 0)*GN;
        const float* p1 = Ps + (size_t)(wid*4 + 1)*GN;
        const float* p2 = Ps + (size_t)(wid*4 + 2)*GN;
        const float* p3 = Ps + (size_t)(wid*4 + 3)*GN;
        for (int j = 0; j < GN; j += 4) {
            float4 pp0 = *(const float4*)(p0 + j);
            float4 pp1 = *(const float4*)(p1 + j);
            float4 pp2 = *(const float4*)(p2 + j);
            float4 pp3 = *(const float4*)(p3 + j);
            #pragma unroll
            for (int jj = 0; jj < 4; jj++) {
                float v0 = Vs[(j + jj)*64 + lane];
                float v1 = Vs[(j + jj)*64 + lane + 32];
                float w0 = jj==0 ? pp0.x : jj==1 ? pp0.y : jj==2 ? pp0.z : pp0.w;
                float w1 = jj==0 ? pp1.x : jj==1 ? pp1.y : jj==2 ? pp1.z : pp1.w;
                float w2 = jj==0 ? pp2.x : jj==1 ? pp2.y : jj==2 ? pp2.z : pp2.w;
                float w3 = jj==0 ? pp3.x : jj==1 ? pp3.y : jj==2 ? pp3.z : pp3.w;
                cA0 += w0*v0; cB0 += w0*v1;
                cA1 += w1*v0; cB1 += w1*v1;
                cA2 += w2*v0; cB2 += w2*v1;
                cA3 += w3*v0; cB3 += w3*v1;
            }
        }

        // store ctx tf32-rounded (feeds the tf32 output GEMM)
        {
            size_t base = ((size_t)(b*GN + i0))*GD + h*GHD;
            CTX[base + lane]             = __uint_as_float(tf32_rna(cA0));
            CTX[base + lane + 32]        = __uint_as_float(tf32_rna(cB0));
            CTX[base + GD + lane]        = __uint_as_float(tf32_rna(cA1));
            CTX[base + GD + lane + 32]   = __uint_as_float(tf32_rna(cB1));
            CTX[base + 2*GD + lane]      = __uint_as_float(tf32_rna(cA2));
            CTX[base + 2*GD + lane + 32] = __uint_as_float(tf32_rna(cB2));
            CTX[base + 3*GD + lane]      = __uint_as_float(tf32_rna(cA3));
            CTX[base + 3*GD + lane + 32] = __uint_as_float(tf32_rna(cB3));
        }
    }
}

// ---------------- launch ----------------------------------------------------
extern "C" void kernel_launch(void* const* d_in, const int* in_sizes, int n_in,
                              void* d_out, int out_size)
{
    const float* hs   = (const float*)d_in[0];
    const float* temp = (const float*)d_in[1];
    const float* Wq   = (const float*)d_in[2];
    const float* bq   = (const float*)d_in[3];
    const float* Wk   = (const float*)d_in[4];
    const float* bk   = (const float*)d_in[5];
    const float* Wv   = (const float*)d_in[6];
    const float* bv   = (const float*)d_in[7];
    const float* Wo   = (const float*)d_in[8];
    const float* bo   = (const float*)d_in[9];
    const float* Wsig = (const float*)d_in[10];
    const float* bsig = (const float*)d_in[11];
    float* out = (float*)d_out;

    float *gq, *gk, *gv, *gctx, *ghs, *gw;
    cudaGetSymbolAddress((void**)&gq,   g_q);
    cudaGetSymbolAddress((void**)&gk,   g_k);
    cudaGetSymbolAddress((void**)&gv,   g_v);
    cudaGetSymbolAddress((void**)&gctx, g_ctx);
    cudaGetSymbolAddress((void**)&ghs,  g_hs);
    cudaGetSymbolAddress((void**)&gw,   g_w);

    cudaFuncSetAttribute(attn_kernel,
                         cudaFuncAttributeMaxDynamicSharedMemorySize,
                         ATT_SMEM_BYTES);
    cudaFuncSetAttribute(mma_gemm,
                         cudaFuncAttributeMaxDynamicSharedMemorySize,
                         GEMM_SMEM);

    float* rwq = gw + 0ull*GD*GD;
    float* rwk = gw + 1ull*GD*GD;
    float* rwv = gw + 2ull*GD*GD;
    float* rwo = gw + 3ull*GD*GD;

    const int nhs4 = GM*GD/4, nw4 = GD*GD/4;
    round_tf32<<<(nhs4 + 255)/256, 256>>>(hs, ghs, nhs4);
    round_tf32<<<(nw4 + 255)/256, 256>>>(Wq, rwq, nw4);
    round_tf32<<<(nw4 + 255)/256, 256>>>(Wk, rwk, nw4);
    round_tf32<<<(nw4 + 255)/256, 256>>>(Wv, rwv, nw4);
    round_tf32<<<(nw4 + 255)/256, 256>>>(Wo, rwo, nw4);

    dim3 gg(GD/BN, GM/BM);   // (6, 98)
    mma_gemm<<<gg, 256, GEMM_SMEM>>>(ghs,  rwq, bq, gq, 1);
    mma_gemm<<<gg, 256, GEMM_SMEM>>>(ghs,  rwk, bk, gk, 1);
    mma_gemm<<<gg, 256, GEMM_SMEM>>>(ghs,  rwv, bv, gv, 1);
    attn_kernel<<<GB*GH, 512, ATT_SMEM_BYTES>>>(gq, gk, gv, Wsig, bsig, temp, gctx);
    mma_gemm<<<gg, 256, GEMM_SMEM>>>(gctx, rwo, bo, out, 0);
}